// round 12
// baseline (speedup 1.0000x reference)
#include <cuda_runtime.h>
#include <cuda_bf16.h>
#include <cstdint>

#define B_  32
#define T_  256
#define V_  32000
#define H_  512
#define G3  1536

// ---------------- scratch (device globals; no allocations allowed) ----------
__device__ float g_gi0[(size_t)T_ * B_ * G3];     // [t][b][3H] layer-0 input gates
__device__ float g_h   [B_ * H_];                 // threaded hidden
__device__ float g_h1  [B_ * H_];                 // hidden after layer 0
__device__ float g_outs[(size_t)T_ * B_ * H_];    // [t][b][H] scan outputs
__device__ __nv_bfloat16 g_Whi[(size_t)V_ * H_];  // Wout bf16 hi plane
__device__ __nv_bfloat16 g_Wlo[(size_t)V_ * H_];  // Wout bf16 lo plane
__device__ __nv_bfloat16 g_Ahi[(size_t)T_ * B_ * H_];
__device__ __nv_bfloat16 g_Alo[(size_t)T_ * B_ * H_];
__device__ unsigned g_count;
__device__ volatile unsigned g_gen;

// ---------------- packed f32x2 helpers -------------------------------------
__device__ __forceinline__ unsigned long long dup2(float x) {
    unsigned long long r; asm("mov.b64 %0, {%1,%1};" : "=l"(r) : "f"(x)); return r;
}
__device__ __forceinline__ unsigned long long f2u(float x, float y) {
    unsigned long long r; asm("mov.b64 %0, {%1,%2};" : "=l"(r) : "f"(x), "f"(y)); return r;
}
__device__ __forceinline__ float2 u2f(unsigned long long v) {
    float2 f; asm("mov.b64 {%0,%1}, %2;" : "=f"(f.x), "=f"(f.y) : "l"(v)); return f;
}
__device__ __forceinline__ unsigned long long fma2(unsigned long long a,
                                                   unsigned long long b,
                                                   unsigned long long c) {
    unsigned long long d;
    asm("fma.rn.f32x2 %0, %1, %2, %3;" : "=l"(d) : "l"(a), "l"(b), "l"(c));
    return d;
}
__device__ __forceinline__ unsigned long long add2(unsigned long long a,
                                                   unsigned long long b) {
    unsigned long long d;
    asm("add.rn.f32x2 %0, %1, %2;" : "=l"(d) : "l"(a), "l"(b));
    return d;
}
__device__ __forceinline__ float sigm(float x) { return 1.f / (1.f + __expf(-x)); }

__device__ __forceinline__ uint32_t smem_u32(const void* p) {
    uint32_t a;
    asm("{ .reg .u64 t; cvta.to.shared.u64 t, %1; cvt.u32.u64 %0, t; }" : "=r"(a) : "l"(p));
    return a;
}

// ---------------- mma.sync / ldmatrix / cp.async helpers --------------------
__device__ __forceinline__ void ldsm4(uint32_t* r, uint32_t addr) {
    asm volatile("ldmatrix.sync.aligned.m8n8.x4.shared.b16 {%0,%1,%2,%3}, [%4];"
        : "=r"(r[0]), "=r"(r[1]), "=r"(r[2]), "=r"(r[3]) : "r"(addr));
}
__device__ __forceinline__ void mma16816(float* c, const uint32_t* a,
                                         uint32_t b0, uint32_t b1) {
    asm volatile("mma.sync.aligned.m16n8k16.row.col.f32.bf16.bf16.f32 "
        "{%0,%1,%2,%3}, {%4,%5,%6,%7}, {%8,%9}, {%0,%1,%2,%3};"
        : "+f"(c[0]), "+f"(c[1]), "+f"(c[2]), "+f"(c[3])
        : "r"(a[0]), "r"(a[1]), "r"(a[2]), "r"(a[3]), "r"(b0), "r"(b1));
}
__device__ __forceinline__ void cpa16(uint32_t d, const void* s) {
    asm volatile("cp.async.cg.shared.global [%0], [%1], 16;" :: "r"(d), "l"(s) : "memory");
}
__device__ __forceinline__ void cpa_commit() {
    asm volatile("cp.async.commit_group;" ::: "memory");
}
template <int N>
__device__ __forceinline__ void cpa_wait() {
    asm volatile("cp.async.wait_group %0;" :: "n"(N) : "memory");
}

// ---------------- grid barrier (proven atomic version) ----------------------
__device__ __forceinline__ void gbar(unsigned nb) {
    __syncthreads();
    if (threadIdx.x == 0) {
        unsigned gen = g_gen;
        __threadfence();
        if (atomicAdd(&g_count, 1u) == nb - 1u) {
            g_count = 0u;
            __threadfence();
            g_gen = gen + 1u;
        } else {
            while (g_gen == gen) { }
            __threadfence();
        }
    }
    __syncthreads();
}

// ============================================================================
// bf16 hi/lo split converters
// ============================================================================
__global__ void conv_w(const float* __restrict__ src) {
    int i = blockIdx.x * 256 + threadIdx.x;           // per float4
    if (i >= V_ * H_ / 4) return;
    float4 v = ((const float4*)src)[i];
    __nv_bfloat16 h0 = __float2bfloat16(v.x), h1 = __float2bfloat16(v.y);
    __nv_bfloat16 h2 = __float2bfloat16(v.z), h3 = __float2bfloat16(v.w);
    __nv_bfloat162* hp = (__nv_bfloat162*)g_Whi;
    __nv_bfloat162* lp = (__nv_bfloat162*)g_Wlo;
    hp[i * 2]     = __nv_bfloat162(h0, h1);
    hp[i * 2 + 1] = __nv_bfloat162(h2, h3);
    lp[i * 2]     = __nv_bfloat162(__float2bfloat16(v.x - __bfloat162float(h0)),
                                   __float2bfloat16(v.y - __bfloat162float(h1)));
    lp[i * 2 + 1] = __nv_bfloat162(__float2bfloat16(v.z - __bfloat162float(h2)),
                                   __float2bfloat16(v.w - __bfloat162float(h3)));
}
__global__ void conv_a() {
    int i = blockIdx.x * 256 + threadIdx.x;
    if (i >= T_ * B_ * H_ / 4) return;
    float4 v = ((const float4*)g_outs)[i];
    __nv_bfloat16 h0 = __float2bfloat16(v.x), h1 = __float2bfloat16(v.y);
    __nv_bfloat16 h2 = __float2bfloat16(v.z), h3 = __float2bfloat16(v.w);
    __nv_bfloat162* hp = (__nv_bfloat162*)g_Ahi;
    __nv_bfloat162* lp = (__nv_bfloat162*)g_Alo;
    hp[i * 2]     = __nv_bfloat162(h0, h1);
    hp[i * 2 + 1] = __nv_bfloat162(h2, h3);
    lp[i * 2]     = __nv_bfloat162(__float2bfloat16(v.x - __bfloat162float(h0)),
                                   __float2bfloat16(v.y - __bfloat162float(h1)));
    lp[i * 2 + 1] = __nv_bfloat162(__float2bfloat16(v.z - __bfloat162float(h2)),
                                   __float2bfloat16(v.w - __bfloat162float(h3)));
}

// ============================================================================
// init_h: zero the threaded hidden state (also shifts scan into ncu slot 4)
// ============================================================================
__global__ void init_h() {
    int i = blockIdx.x * 256 + threadIdx.x;
    if (i < B_ * H_) g_h[i] = 0.f;
}

// ============================================================================
// gi0 = gather(emb, x) @ Wih0^T + bih0   (SIMT GEMM, small: 12.9 GF)
// ============================================================================
__global__ void __launch_bounds__(256, 2)
gemm_gi0(const float* __restrict__ Aemb, const float* __restrict__ Bw,
         const float* __restrict__ bias, const int* __restrict__ xtok)
{
    __shared__ float As[16][132];
    __shared__ float Bs[16][132];
    __shared__ int   rowtok[128];

    const int tid = threadIdx.x;
    const int tx  = tid & 15;
    const int ty  = tid >> 4;
    const int m0  = blockIdx.y * 128;
    const int n0  = blockIdx.x * 128;

    if (tid < 128) {
        int m = m0 + tid;
        rowtok[tid] = xtok[(m & 31) * T_ + (m >> 5)];
    }
    __syncthreads();

    unsigned long long acc[8][4];
#pragma unroll
    for (int i = 0; i < 8; i++)
#pragma unroll
        for (int q = 0; q < 4; q++) acc[i][q] = 0ull;

    for (int k0 = 0; k0 < H_; k0 += 16) {
#pragma unroll
        for (int rep = 0; rep < 2; rep++) {
            int lin = tid + rep * 256;
            int row = lin >> 2;
            int kg  = lin & 3;
            float4 va = *(const float4*)(Aemb + (size_t)rowtok[row] * H_ + k0 + kg * 4);
            As[kg * 4 + 0][row] = va.x; As[kg * 4 + 1][row] = va.y;
            As[kg * 4 + 2][row] = va.z; As[kg * 4 + 3][row] = va.w;
            float4 vb = *(const float4*)(Bw + (size_t)(n0 + row) * H_ + k0 + kg * 4);
            Bs[kg * 4 + 0][row] = vb.x; Bs[kg * 4 + 1][row] = vb.y;
            Bs[kg * 4 + 2][row] = vb.z; Bs[kg * 4 + 3][row] = vb.w;
        }
        __syncthreads();

#pragma unroll
        for (int kk = 0; kk < 16; kk++) {
            float4 a0 = *(const float4*)&As[kk][ty * 8];
            float4 a1 = *(const float4*)&As[kk][ty * 8 + 4];
            const unsigned long long* bp = (const unsigned long long*)&Bs[kk][tx * 8];
            unsigned long long b0 = bp[0], b1 = bp[1], b2 = bp[2], b3 = bp[3];
            unsigned long long ad[8];
            ad[0] = dup2(a0.x); ad[1] = dup2(a0.y); ad[2] = dup2(a0.z); ad[3] = dup2(a0.w);
            ad[4] = dup2(a1.x); ad[5] = dup2(a1.y); ad[6] = dup2(a1.z); ad[7] = dup2(a1.w);
#pragma unroll
            for (int i = 0; i < 8; i++) {
                acc[i][0] = fma2(ad[i], b0, acc[i][0]);
                acc[i][1] = fma2(ad[i], b1, acc[i][1]);
                acc[i][2] = fma2(ad[i], b2, acc[i][2]);
                acc[i][3] = fma2(ad[i], b3, acc[i][3]);
            }
        }
        __syncthreads();
    }

    float bb[8];
#pragma unroll
    for (int q = 0; q < 8; q++) bb[q] = bias[n0 + tx * 8 + q];
#pragma unroll
    for (int i = 0; i < 8; i++) {
        int m = m0 + ty * 8 + i;
        float2 c0 = u2f(acc[i][0]);
        float2 c1 = u2f(acc[i][1]);
        float2 c2 = u2f(acc[i][2]);
        float2 c3 = u2f(acc[i][3]);
        float* crow = g_gi0 + (size_t)m * G3 + n0 + tx * 8;
        *(float4*)(crow)     = make_float4(c0.x + bb[0], c0.y + bb[1], c1.x + bb[2], c1.y + bb[3]);
        *(float4*)(crow + 4) = make_float4(c2.x + bb[4], c2.y + bb[5], c3.x + bb[6], c3.y + bb[7]);
    }
}

// ============================================================================
// Recurrent scan v4: 128 blocks x 512 threads.
// Block = 8 j x 2 batch-groups (16 batches) -> per-SM weight footprint 144KB,
// fully L1D-resident across all 256 steps. Inner loops identical to R4/R7.
// Biases hoisted out of the t-loop; gi0 prefetched at step top.
// ============================================================================
__global__ void __launch_bounds__(512, 1)
scan_kernel(const float* __restrict__ Whh0,
            const float* __restrict__ Wih1,
            const float* __restrict__ Whh1,
            const float* __restrict__ bih1,
            const float* __restrict__ bhh0,
            const float* __restrict__ bhh1)
{
    __shared__ __align__(16) float hs[16 * H_];   // 32 KB: 16-batch slab

    const unsigned NB = gridDim.x;        // 128
    const int tid  = threadIdx.x;
    const int bid  = blockIdx.x;
    const int lane = tid & 31;
    const int wid  = tid >> 5;
    const int jj   = wid >> 1;            // 0..7
    const int bgl  = wid & 1;             // 0..1 (8-batch group within slab)
    const int jb   = bid >> 1;            // 0..63 (j-slice)
    const int bh   = bid & 1;             // batch half (16 batches)
    const int j    = jb * 8 + jj;         // 0..511
    const int bl0  = bgl * 8;             // local batch base in slab

    // ---- loop-invariant biases (hoisted out of the scan) ----
    const float b0r = bhh0[j], b0z = bhh0[j + 512], b0n = bhh0[j + 1024];
    const float brs = bih1[j] + bhh1[j];
    const float bzs = bih1[j + 512] + bhh1[j + 512];
    const float bin = bih1[j + 1024];
    const float bhn = bhh1[j + 1024];

    for (int t = 0; t < T_; t++) {
        // gi0 prefetch (hidden under staging + L0 dot)
        float giR = 0.f, giZ = 0.f, giN = 0.f;
        if (lane < 8) {
            const float* gp = g_gi0 + ((size_t)t * B_ + bh * 16 + bl0 + lane) * G3;
            giR = gp[j]; giZ = gp[j + 512]; giN = gp[j + 1024];
        }

        // ---- stage h slab (16 batches, 32 KB) ----
        for (int i = tid; i < 2048; i += 512)
            *(float4*)&hs[i * 4] = *(const float4*)&g_h[bh * 16 * H_ + i * 4];
        __syncthreads();

        // ---- layer 0 dot ----
        {
            unsigned long long aR[4], aZ[4], aN[4];
#pragma unroll
            for (int p = 0; p < 4; p++) { aR[p] = 0; aZ[p] = 0; aN[p] = 0; }
#pragma unroll 4
            for (int k = lane; k < H_; k += 32) {
                unsigned long long wr2 = dup2(Whh0[(size_t)j * H_ + k]);
                unsigned long long wz2 = dup2(Whh0[(size_t)(j + 512) * H_ + k]);
                unsigned long long wn2 = dup2(Whh0[(size_t)(j + 1024) * H_ + k]);
#pragma unroll
                for (int p = 0; p < 4; p++) {
                    unsigned long long h2 =
                        f2u(hs[(bl0 + 2 * p) * H_ + k], hs[(bl0 + 2 * p + 1) * H_ + k]);
                    aR[p] = fma2(wr2, h2, aR[p]);
                    aZ[p] = fma2(wz2, h2, aZ[p]);
                    aN[p] = fma2(wn2, h2, aN[p]);
                }
            }
#pragma unroll
            for (int p = 0; p < 4; p++)
#pragma unroll
                for (int off = 16; off > 0; off >>= 1) {
                    aR[p] = add2(aR[p], __shfl_xor_sync(0xffffffffu, aR[p], off));
                    aZ[p] = add2(aZ[p], __shfl_xor_sync(0xffffffffu, aZ[p], off));
                    aN[p] = add2(aN[p], __shfl_xor_sync(0xffffffffu, aN[p], off));
                }
            if (lane < 8) {
                int p = lane >> 1, hi = lane & 1;
                float2 fr = u2f(aR[p]), fz = u2f(aZ[p]), fn = u2f(aN[p]);
                float ghr = (hi ? fr.y : fr.x) + b0r;
                float ghz = (hi ? fz.y : fz.x) + b0z;
                float ghn = (hi ? fn.y : fn.x) + b0n;
                float r = sigm(giR + ghr);
                float z = sigm(giZ + ghz);
                float n = tanhf(giN + r * ghn);
                int b = bh * 16 + bl0 + lane;
                float hold = hs[(bl0 + lane) * H_ + j];
                g_h1[(size_t)b * H_ + j] = (1.f - z) * n + z * hold;
            }
        }
        gbar(NB);

        // ---- stage h1 slab ----
        for (int i = tid; i < 2048; i += 512)
            *(float4*)&hs[i * 4] = *(const float4*)&g_h1[bh * 16 * H_ + i * 4];
        __syncthreads();

        // ---- layer 1 dot ----
        {
            unsigned long long aIR[4], aIZ[4], aIN[4], aHR[4], aHZ[4], aHN[4];
#pragma unroll
            for (int p = 0; p < 4; p++) {
                aIR[p] = 0; aIZ[p] = 0; aIN[p] = 0;
                aHR[p] = 0; aHZ[p] = 0; aHN[p] = 0;
            }
#pragma unroll 4
            for (int k = lane; k < H_; k += 32) {
                unsigned long long wir = dup2(Wih1[(size_t)j * H_ + k]);
                unsigned long long wiz = dup2(Wih1[(size_t)(j + 512) * H_ + k]);
                unsigned long long win = dup2(Wih1[(size_t)(j + 1024) * H_ + k]);
                unsigned long long whr = dup2(Whh1[(size_t)j * H_ + k]);
                unsigned long long whz = dup2(Whh1[(size_t)(j + 512) * H_ + k]);
                unsigned long long whn = dup2(Whh1[(size_t)(j + 1024) * H_ + k]);
#pragma unroll
                for (int p = 0; p < 4; p++) {
                    unsigned long long h2 =
                        f2u(hs[(bl0 + 2 * p) * H_ + k], hs[(bl0 + 2 * p + 1) * H_ + k]);
                    aIR[p] = fma2(wir, h2, aIR[p]);
                    aIZ[p] = fma2(wiz, h2, aIZ[p]);
                    aIN[p] = fma2(win, h2, aIN[p]);
                    aHR[p] = fma2(whr, h2, aHR[p]);
                    aHZ[p] = fma2(whz, h2, aHZ[p]);
                    aHN[p] = fma2(whn, h2, aHN[p]);
                }
            }
#pragma unroll
            for (int p = 0; p < 4; p++)
#pragma unroll
                for (int off = 16; off > 0; off >>= 1) {
                    aIR[p] = add2(aIR[p], __shfl_xor_sync(0xffffffffu, aIR[p], off));
                    aIZ[p] = add2(aIZ[p], __shfl_xor_sync(0xffffffffu, aIZ[p], off));
                    aIN[p] = add2(aIN[p], __shfl_xor_sync(0xffffffffu, aIN[p], off));
                    aHR[p] = add2(aHR[p], __shfl_xor_sync(0xffffffffu, aHR[p], off));
                    aHZ[p] = add2(aHZ[p], __shfl_xor_sync(0xffffffffu, aHZ[p], off));
                    aHN[p] = add2(aHN[p], __shfl_xor_sync(0xffffffffu, aHN[p], off));
                }
            if (lane < 8) {
                int p = lane >> 1, hi = lane & 1;
                float2 f;
                f = u2f(aIR[p]); float ir  = (hi ? f.y : f.x);
                f = u2f(aIZ[p]); float iz  = (hi ? f.y : f.x);
                f = u2f(aIN[p]); float inn = (hi ? f.y : f.x);
                f = u2f(aHR[p]); float hr  = (hi ? f.y : f.x);
                f = u2f(aHZ[p]); float hz  = (hi ? f.y : f.x);
                f = u2f(aHN[p]); float hn  = (hi ? f.y : f.x);
                float r = sigm(ir + hr + brs);
                float z = sigm(iz + hz + bzs);
                float n = tanhf(inn + bin + r * (hn + bhn));
                int b = bh * 16 + bl0 + lane;
                float h1v = hs[(bl0 + lane) * H_ + j];
                float h2v = (1.f - z) * n + z * h1v;
                g_h[(size_t)b * H_ + j] = h2v;
                g_outs[((size_t)t * B_ + b) * H_ + j] = h2v;
            }
        }
        gbar(NB);
    }
}

// ============================================================================
// Projection (R7-proven): mma.sync bf16 hi/lo split, CTA 128x128, BK=32,
// 3-stage cp.async pipeline, 96KB smem -> 2 CTAs/SM.
// ============================================================================
#define PST 32768   // stage stride: Ahi 8K | Alo 8K | Bhi 8K | Blo 8K

__global__ void __launch_bounds__(256, 2)
proj_mma(const float* __restrict__ bout, float* __restrict__ out)
{
    extern __shared__ char psm[];
    const int tid  = threadIdx.x;
    const int lane = tid & 31;
    const int warp = tid >> 5;
    const int wm   = warp & 1;            // 2 warps along M (64 rows each)
    const int wn   = warp >> 1;           // 4 warps along N (32 cols each)
    const int m0   = blockIdx.x * 128;    // m fastest -> B tiles shared via L2
    const int n0   = blockIdx.y * 128;
    const uint32_t sb = smem_u32(psm);

    const int lr = tid >> 1;
    const int cbs = (tid & 1) * 2;        // 16B-chunk base within 64B row

    const int lrA = lane & 15;
    const int lch = lane >> 4;
    const int lx  = (lrA >> 1) & 3;

    float acc[4][4][4];
#pragma unroll
    for (int a = 0; a < 4; a++)
#pragma unroll
        for (int b = 0; b < 4; b++)
#pragma unroll
            for (int c = 0; c < 4; c++) acc[a][b][c] = 0.f;

    const __nv_bfloat16* srcAh = g_Ahi + (size_t)(m0 + lr) * H_;
    const __nv_bfloat16* srcAl = g_Alo + (size_t)(m0 + lr) * H_;
    const __nv_bfloat16* srcBh = g_Whi + (size_t)(n0 + lr) * H_;
    const __nv_bfloat16* srcBl = g_Wlo + (size_t)(n0 + lr) * H_;
    const uint32_t drow = sb + lr * 64;
    const int lsw = (lr >> 1) & 3;

#define ISSUE(kc, s) do {                                                      \
        int k0 = (kc) * 32;                                                    \
        uint32_t stb = drow + (uint32_t)(s) * PST;                             \
        _Pragma("unroll")                                                      \
        for (int c = 0; c < 2; c++) {                                          \
            uint32_t dsw = stb + (uint32_t)(((cbs + c) ^ lsw) << 4);           \
            int ko = k0 + (cbs + c) * 8;                                       \
            cpa16(dsw,         srcAh + ko);                                    \
            cpa16(dsw + 8192,  srcAl + ko);                                    \
            cpa16(dsw + 16384, srcBh + ko);                                    \
            cpa16(dsw + 24576, srcBl + ko);                                    \
        }                                                                      \
        cpa_commit();                                                          \
    } while (0)

    ISSUE(0, 0);
    ISSUE(1, 1);

    for (int kc = 0; kc < 16; kc++) {
        if (kc < 14)       { ISSUE(kc + 2, (kc + 2) % 3); cpa_wait<2>(); }
        else if (kc == 14) { cpa_wait<1>(); }
        else               { cpa_wait<0>(); }
        __syncthreads();

        const int s = kc % 3;
        const uint32_t aRowH = sb + s * PST + (wm * 64 + lrA) * 64;
        const uint32_t aRowL = aRowH + 8192;
        const uint32_t bRowH = sb + s * PST + 16384 + (wn * 32 + lrA) * 64;
        const uint32_t bRowL = bRowH + 8192;

#pragma unroll
        for (int k16 = 0; k16 < 2; k16++) {
            const uint32_t csw = (uint32_t)(((k16 * 2 + lch) ^ lx) << 4);
            uint32_t ah[4][4], al[4][4], bh[2][4], bl[2][4];
#pragma unroll
            for (int fm = 0; fm < 4; fm++) {
                ldsm4(ah[fm], aRowH + fm * 1024 + csw);
                ldsm4(al[fm], aRowL + fm * 1024 + csw);
            }
#pragma unroll
            for (int pr = 0; pr < 2; pr++) {
                ldsm4(bh[pr], bRowH + pr * 1024 + csw);
                ldsm4(bl[pr], bRowL + pr * 1024 + csw);
            }
#pragma unroll
            for (int fm = 0; fm < 4; fm++)
#pragma unroll
                for (int pr = 0; pr < 2; pr++)
#pragma unroll
                    for (int su = 0; su < 2; su++) {
                        float* c = acc[fm][pr * 2 + su];
                        mma16816(c, ah[fm], bh[pr][su], bh[pr][su + 2]);
                        mma16816(c, ah[fm], bl[pr][su], bl[pr][su + 2]);
                        mma16816(c, al[fm], bh[pr][su], bh[pr][su + 2]);
                    }
        }
        __syncthreads();
    }

    // ---- epilogue: direct STG ----
    const int qr = lane >> 2;
    const int qc = (lane & 3) * 2;
#pragma unroll
    for (int fm = 0; fm < 4; fm++) {
        int mA = m0 + wm * 64 + fm * 16 + qr;
        int mB = mA + 8;
        size_t rowA = (size_t)((mA & 31) * T_ + (mA >> 5)) * V_;
        size_t rowB = (size_t)((mB & 31) * T_ + (mB >> 5)) * V_;
#pragma unroll
        for (int fn = 0; fn < 4; fn++) {
            int n = n0 + wn * 32 + fn * 8 + qc;
            float2 bb = *(const float2*)(bout + n);
            float* c = acc[fm][fn];
            *(float2*)(out + rowA + n) = make_float2(c[0] + bb.x, c[1] + bb.y);
            *(float2*)(out + rowB + n) = make_float2(c[2] + bb.x, c[3] + bb.y);
        }
    }
}

// ============================================================================
extern "C" void kernel_launch(void* const* d_in, const int* in_sizes, int n_in,
                              void* d_out, int out_size) {
    (void)in_sizes; (void)n_in; (void)out_size;
    const int*   x    = (const int*)  d_in[0];
    const float* emb  = (const float*)d_in[1];
    const float* Wih  = (const float*)d_in[2];
    const float* Whh  = (const float*)d_in[3];
    const float* bih  = (const float*)d_in[4];
    const float* bhh  = (const float*)d_in[5];
    const float* Wout = (const float*)d_in[6];
    const float* bout = (const float*)d_in[7];
    float* out = (float*)d_out;

    cudaFuncSetAttribute(proj_mma, cudaFuncAttributeMaxDynamicSharedMemorySize, 3 * PST);

    // 1) Wout -> bf16 hi/lo planes
    conv_w<<<(V_ * H_ / 4 + 255) / 256, 256>>>(Wout);

    // 2) gi0 = gather(emb, x) @ Wih0^T + bih0
    gemm_gi0<<<dim3(G3 / 128, (T_ * B_) / 128), 256>>>(emb, Wih, bih, x);

    // 3) zero hidden state (also puts scan in the ncu -s 5 profile slot)
    init_h<<<(B_ * H_ + 255) / 256, 256>>>();

    // 4) 256-step GRU scan (L1D-resident weights: 8 j x 2 bg per block)
    scan_kernel<<<128, 512>>>(Whh,
                              Wih + (size_t)G3 * H_,
                              Whh + (size_t)G3 * H_,
                              bih + G3,
                              bhh,
                              bhh + G3);

    // 5) outs -> bf16 hi/lo planes
    conv_a<<<(T_ * B_ * H_ / 4 + 255) / 256, 256>>>();

    // 6) logits = outs @ Wout^T + bout  (BK=32, 3-stage, 2 CTAs/SM)
    proj_mma<<<dim3((T_ * B_) / 128, V_ / 128), 256, 3 * PST>>>(bout, out);
}

// round 13
// speedup vs baseline: 1.0201x; 1.0201x over previous
#include <cuda_runtime.h>
#include <cuda_bf16.h>
#include <cstdint>

#define B_  32
#define T_  256
#define V_  32000
#define H_  512
#define G3  1536

// ---------------- scratch (device globals; no allocations allowed) ----------
__device__ float g_gi0[(size_t)T_ * B_ * G3];     // [t][b][3H] layer-0 input gates
__device__ float g_h   [B_ * H_];                 // threaded hidden
__device__ float g_h1  [B_ * H_];                 // hidden after layer 0
__device__ float g_outs[(size_t)T_ * B_ * H_];    // [t][b][H] scan outputs
__device__ __nv_bfloat16 g_Whi[(size_t)V_ * H_];  // Wout bf16 hi plane
__device__ __nv_bfloat16 g_Wlo[(size_t)V_ * H_];  // Wout bf16 lo plane
__device__ __nv_bfloat16 g_Ahi[(size_t)T_ * B_ * H_];
__device__ __nv_bfloat16 g_Alo[(size_t)T_ * B_ * H_];
__device__ __align__(16) volatile unsigned g_flagsV[128];  // barrier arrival flags
__device__ volatile unsigned g_go;                          // barrier release word

// ---------------- packed f32x2 helpers -------------------------------------
__device__ __forceinline__ unsigned long long dup2(float x) {
    unsigned long long r; asm("mov.b64 %0, {%1,%1};" : "=l"(r) : "f"(x)); return r;
}
__device__ __forceinline__ unsigned long long f2u(float x, float y) {
    unsigned long long r; asm("mov.b64 %0, {%1,%2};" : "=l"(r) : "f"(x), "f"(y)); return r;
}
__device__ __forceinline__ float2 u2f(unsigned long long v) {
    float2 f; asm("mov.b64 {%0,%1}, %2;" : "=f"(f.x), "=f"(f.y) : "l"(v)); return f;
}
__device__ __forceinline__ unsigned long long fma2(unsigned long long a,
                                                   unsigned long long b,
                                                   unsigned long long c) {
    unsigned long long d;
    asm("fma.rn.f32x2 %0, %1, %2, %3;" : "=l"(d) : "l"(a), "l"(b), "l"(c));
    return d;
}
__device__ __forceinline__ unsigned long long add2(unsigned long long a,
                                                   unsigned long long b) {
    unsigned long long d;
    asm("add.rn.f32x2 %0, %1, %2;" : "=l"(d) : "l"(a), "l"(b));
    return d;
}
__device__ __forceinline__ float sigm(float x) { return 1.f / (1.f + __expf(-x)); }

__device__ __forceinline__ uint32_t smem_u32(const void* p) {
    uint32_t a;
    asm("{ .reg .u64 t; cvta.to.shared.u64 t, %1; cvt.u32.u64 %0, t; }" : "=r"(a) : "l"(p));
    return a;
}

// ---------------- mma.sync / ldmatrix / cp.async helpers --------------------
__device__ __forceinline__ void ldsm4(uint32_t* r, uint32_t addr) {
    asm volatile("ldmatrix.sync.aligned.m8n8.x4.shared.b16 {%0,%1,%2,%3}, [%4];"
        : "=r"(r[0]), "=r"(r[1]), "=r"(r[2]), "=r"(r[3]) : "r"(addr));
}
__device__ __forceinline__ void mma16816(float* c, const uint32_t* a,
                                         uint32_t b0, uint32_t b1) {
    asm volatile("mma.sync.aligned.m16n8k16.row.col.f32.bf16.bf16.f32 "
        "{%0,%1,%2,%3}, {%4,%5,%6,%7}, {%8,%9}, {%0,%1,%2,%3};"
        : "+f"(c[0]), "+f"(c[1]), "+f"(c[2]), "+f"(c[3])
        : "r"(a[0]), "r"(a[1]), "r"(a[2]), "r"(a[3]), "r"(b0), "r"(b1));
}
__device__ __forceinline__ void cpa16(uint32_t d, const void* s) {
    asm volatile("cp.async.cg.shared.global [%0], [%1], 16;" :: "r"(d), "l"(s) : "memory");
}
__device__ __forceinline__ void cpa_commit() {
    asm volatile("cp.async.commit_group;" ::: "memory");
}
template <int N>
__device__ __forceinline__ void cpa_wait() {
    asm volatile("cp.async.wait_group %0;" :: "n"(N) : "memory");
}

// ---------------- grid barrier v2: store / checker / broadcast --------------
// arrival: parallel flag stores (no atomics). checker: block 0 warp 0 reads
// all 128 flags (one ld.volatile.v4 per lane). release: single g_go word.
__device__ __forceinline__ void gbarF(unsigned target) {
    __syncthreads();
    if (threadIdx.x == 0) {
        __threadfence();
        g_flagsV[blockIdx.x] = target;
    }
    if (blockIdx.x == 0 && threadIdx.x < 32) {
        const unsigned* fp = (const unsigned*)g_flagsV;
        for (;;) {
            uint4 v;
            asm volatile("ld.volatile.global.v4.u32 {%0,%1,%2,%3}, [%4];"
                : "=r"(v.x), "=r"(v.y), "=r"(v.z), "=r"(v.w)
                : "l"(fp + threadIdx.x * 4) : "memory");
            bool ok = (int)(v.x - target) >= 0 && (int)(v.y - target) >= 0 &&
                      (int)(v.z - target) >= 0 && (int)(v.w - target) >= 0;
            if (__all_sync(0xffffffffu, ok)) break;
        }
        if (threadIdx.x == 0) g_go = target;
    }
    if (threadIdx.x == 0) {
        while ((int)(g_go - target) < 0) { }
        __threadfence();
    }
    __syncthreads();
}

// ============================================================================
// bf16 hi/lo split converters
// ============================================================================
__global__ void conv_w(const float* __restrict__ src) {
    int i = blockIdx.x * 256 + threadIdx.x;           // per float4
    if (i >= V_ * H_ / 4) return;
    float4 v = ((const float4*)src)[i];
    __nv_bfloat16 h0 = __float2bfloat16(v.x), h1 = __float2bfloat16(v.y);
    __nv_bfloat16 h2 = __float2bfloat16(v.z), h3 = __float2bfloat16(v.w);
    __nv_bfloat162* hp = (__nv_bfloat162*)g_Whi;
    __nv_bfloat162* lp = (__nv_bfloat162*)g_Wlo;
    hp[i * 2]     = __nv_bfloat162(h0, h1);
    hp[i * 2 + 1] = __nv_bfloat162(h2, h3);
    lp[i * 2]     = __nv_bfloat162(__float2bfloat16(v.x - __bfloat162float(h0)),
                                   __float2bfloat16(v.y - __bfloat162float(h1)));
    lp[i * 2 + 1] = __nv_bfloat162(__float2bfloat16(v.z - __bfloat162float(h2)),
                                   __float2bfloat16(v.w - __bfloat162float(h3)));
}
__global__ void conv_a() {
    int i = blockIdx.x * 256 + threadIdx.x;
    if (i >= T_ * B_ * H_ / 4) return;
    float4 v = ((const float4*)g_outs)[i];
    __nv_bfloat16 h0 = __float2bfloat16(v.x), h1 = __float2bfloat16(v.y);
    __nv_bfloat16 h2 = __float2bfloat16(v.z), h3 = __float2bfloat16(v.w);
    __nv_bfloat162* hp = (__nv_bfloat162*)g_Ahi;
    __nv_bfloat162* lp = (__nv_bfloat162*)g_Alo;
    hp[i * 2]     = __nv_bfloat162(h0, h1);
    hp[i * 2 + 1] = __nv_bfloat162(h2, h3);
    lp[i * 2]     = __nv_bfloat162(__float2bfloat16(v.x - __bfloat162float(h0)),
                                   __float2bfloat16(v.y - __bfloat162float(h1)));
    lp[i * 2 + 1] = __nv_bfloat162(__float2bfloat16(v.z - __bfloat162float(h2)),
                                   __float2bfloat16(v.w - __bfloat162float(h3)));
}

// ============================================================================
// init_h: zero hidden state (keeps scan in the ncu -s 5 profile slot)
// ============================================================================
__global__ void init_h() {
    int i = blockIdx.x * 256 + threadIdx.x;
    if (i < B_ * H_) g_h[i] = 0.f;
}

// ============================================================================
// gi0 = gather(emb, x) @ Wih0^T + bih0   (SIMT GEMM, small: 12.9 GF)
// ============================================================================
__global__ void __launch_bounds__(256, 2)
gemm_gi0(const float* __restrict__ Aemb, const float* __restrict__ Bw,
         const float* __restrict__ bias, const int* __restrict__ xtok)
{
    __shared__ float As[16][132];
    __shared__ float Bs[16][132];
    __shared__ int   rowtok[128];

    const int tid = threadIdx.x;
    const int tx  = tid & 15;
    const int ty  = tid >> 4;
    const int m0  = blockIdx.y * 128;
    const int n0  = blockIdx.x * 128;

    if (tid < 128) {
        int m = m0 + tid;
        rowtok[tid] = xtok[(m & 31) * T_ + (m >> 5)];
    }
    __syncthreads();

    unsigned long long acc[8][4];
#pragma unroll
    for (int i = 0; i < 8; i++)
#pragma unroll
        for (int q = 0; q < 4; q++) acc[i][q] = 0ull;

    for (int k0 = 0; k0 < H_; k0 += 16) {
#pragma unroll
        for (int rep = 0; rep < 2; rep++) {
            int lin = tid + rep * 256;
            int row = lin >> 2;
            int kg  = lin & 3;
            float4 va = *(const float4*)(Aemb + (size_t)rowtok[row] * H_ + k0 + kg * 4);
            As[kg * 4 + 0][row] = va.x; As[kg * 4 + 1][row] = va.y;
            As[kg * 4 + 2][row] = va.z; As[kg * 4 + 3][row] = va.w;
            float4 vb = *(const float4*)(Bw + (size_t)(n0 + row) * H_ + k0 + kg * 4);
            Bs[kg * 4 + 0][row] = vb.x; Bs[kg * 4 + 1][row] = vb.y;
            Bs[kg * 4 + 2][row] = vb.z; Bs[kg * 4 + 3][row] = vb.w;
        }
        __syncthreads();

#pragma unroll
        for (int kk = 0; kk < 16; kk++) {
            float4 a0 = *(const float4*)&As[kk][ty * 8];
            float4 a1 = *(const float4*)&As[kk][ty * 8 + 4];
            const unsigned long long* bp = (const unsigned long long*)&Bs[kk][tx * 8];
            unsigned long long b0 = bp[0], b1 = bp[1], b2 = bp[2], b3 = bp[3];
            unsigned long long ad[8];
            ad[0] = dup2(a0.x); ad[1] = dup2(a0.y); ad[2] = dup2(a0.z); ad[3] = dup2(a0.w);
            ad[4] = dup2(a1.x); ad[5] = dup2(a1.y); ad[6] = dup2(a1.z); ad[7] = dup2(a1.w);
#pragma unroll
            for (int i = 0; i < 8; i++) {
                acc[i][0] = fma2(ad[i], b0, acc[i][0]);
                acc[i][1] = fma2(ad[i], b1, acc[i][1]);
                acc[i][2] = fma2(ad[i], b2, acc[i][2]);
                acc[i][3] = fma2(ad[i], b3, acc[i][3]);
            }
        }
        __syncthreads();
    }

    float bb[8];
#pragma unroll
    for (int q = 0; q < 8; q++) bb[q] = bias[n0 + tx * 8 + q];
#pragma unroll
    for (int i = 0; i < 8; i++) {
        int m = m0 + ty * 8 + i;
        float2 c0 = u2f(acc[i][0]);
        float2 c1 = u2f(acc[i][1]);
        float2 c2 = u2f(acc[i][2]);
        float2 c3 = u2f(acc[i][3]);
        float* crow = g_gi0 + (size_t)m * G3 + n0 + tx * 8;
        *(float4*)(crow)     = make_float4(c0.x + bb[0], c0.y + bb[1], c1.x + bb[2], c1.y + bb[3]);
        *(float4*)(crow + 4) = make_float4(c2.x + bb[4], c2.y + bb[5], c3.x + bb[6], c3.y + bb[7]);
    }
}

// ============================================================================
// Recurrent scan v5: identical compute to v4 (R12); only the grid barrier
// changed (atomic counter -> store/checker/broadcast flags).
// 128 blocks x 512 threads; block = 8 j x 2 batch-groups.
// ============================================================================
__global__ void __launch_bounds__(512, 1)
scan_kernel(const float* __restrict__ Whh0,
            const float* __restrict__ Wih1,
            const float* __restrict__ Whh1,
            const float* __restrict__ bih1,
            const float* __restrict__ bhh0,
            const float* __restrict__ bhh1)
{
    __shared__ __align__(16) float hs[16 * H_];   // 32 KB: 16-batch slab

    const int tid  = threadIdx.x;
    const int bid  = blockIdx.x;
    const int lane = tid & 31;
    const int wid  = tid >> 5;
    const int jj   = wid >> 1;            // 0..7
    const int bgl  = wid & 1;             // 0..1 (8-batch group within slab)
    const int jb   = bid >> 1;            // 0..63 (j-slice)
    const int bh   = bid & 1;             // batch half (16 batches)
    const int j    = jb * 8 + jj;         // 0..511
    const int bl0  = bgl * 8;             // local batch base in slab

    // ---- loop-invariant biases ----
    const float b0r = bhh0[j], b0z = bhh0[j + 512], b0n = bhh0[j + 1024];
    const float brs = bih1[j] + bhh1[j];
    const float bzs = bih1[j + 512] + bhh1[j + 512];
    const float bin = bih1[j + 1024];
    const float bhn = bhh1[j + 1024];

    unsigned bt = g_go;   // replay-safe relative barrier base (flags==g_go at exit)

    for (int t = 0; t < T_; t++) {
        // gi0 prefetch (hidden under staging + L0 dot)
        float giR = 0.f, giZ = 0.f, giN = 0.f;
        if (lane < 8) {
            const float* gp = g_gi0 + ((size_t)t * B_ + bh * 16 + bl0 + lane) * G3;
            giR = gp[j]; giZ = gp[j + 512]; giN = gp[j + 1024];
        }

        // ---- stage h slab (16 batches, 32 KB) ----
        for (int i = tid; i < 2048; i += 512)
            *(float4*)&hs[i * 4] = *(const float4*)&g_h[bh * 16 * H_ + i * 4];
        __syncthreads();

        // ---- layer 0 dot ----
        {
            unsigned long long aR[4], aZ[4], aN[4];
#pragma unroll
            for (int p = 0; p < 4; p++) { aR[p] = 0; aZ[p] = 0; aN[p] = 0; }
#pragma unroll 4
            for (int k = lane; k < H_; k += 32) {
                unsigned long long wr2 = dup2(Whh0[(size_t)j * H_ + k]);
                unsigned long long wz2 = dup2(Whh0[(size_t)(j + 512) * H_ + k]);
                unsigned long long wn2 = dup2(Whh0[(size_t)(j + 1024) * H_ + k]);
#pragma unroll
                for (int p = 0; p < 4; p++) {
                    unsigned long long h2 =
                        f2u(hs[(bl0 + 2 * p) * H_ + k], hs[(bl0 + 2 * p + 1) * H_ + k]);
                    aR[p] = fma2(wr2, h2, aR[p]);
                    aZ[p] = fma2(wz2, h2, aZ[p]);
                    aN[p] = fma2(wn2, h2, aN[p]);
                }
            }
#pragma unroll
            for (int p = 0; p < 4; p++)
#pragma unroll
                for (int off = 16; off > 0; off >>= 1) {
                    aR[p] = add2(aR[p], __shfl_xor_sync(0xffffffffu, aR[p], off));
                    aZ[p] = add2(aZ[p], __shfl_xor_sync(0xffffffffu, aZ[p], off));
                    aN[p] = add2(aN[p], __shfl_xor_sync(0xffffffffu, aN[p], off));
                }
            if (lane < 8) {
                int p = lane >> 1, hi = lane & 1;
                float2 fr = u2f(aR[p]), fz = u2f(aZ[p]), fn = u2f(aN[p]);
                float ghr = (hi ? fr.y : fr.x) + b0r;
                float ghz = (hi ? fz.y : fz.x) + b0z;
                float ghn = (hi ? fn.y : fn.x) + b0n;
                float r = sigm(giR + ghr);
                float z = sigm(giZ + ghz);
                float n = tanhf(giN + r * ghn);
                int b = bh * 16 + bl0 + lane;
                float hold = hs[(bl0 + lane) * H_ + j];
                g_h1[(size_t)b * H_ + j] = (1.f - z) * n + z * hold;
            }
        }
        gbarF(++bt);

        // ---- stage h1 slab ----
        for (int i = tid; i < 2048; i += 512)
            *(float4*)&hs[i * 4] = *(const float4*)&g_h1[bh * 16 * H_ + i * 4];
        __syncthreads();

        // ---- layer 1 dot ----
        {
            unsigned long long aIR[4], aIZ[4], aIN[4], aHR[4], aHZ[4], aHN[4];
#pragma unroll
            for (int p = 0; p < 4; p++) {
                aIR[p] = 0; aIZ[p] = 0; aIN[p] = 0;
                aHR[p] = 0; aHZ[p] = 0; aHN[p] = 0;
            }
#pragma unroll 4
            for (int k = lane; k < H_; k += 32) {
                unsigned long long wir = dup2(Wih1[(size_t)j * H_ + k]);
                unsigned long long wiz = dup2(Wih1[(size_t)(j + 512) * H_ + k]);
                unsigned long long win = dup2(Wih1[(size_t)(j + 1024) * H_ + k]);
                unsigned long long whr = dup2(Whh1[(size_t)j * H_ + k]);
                unsigned long long whz = dup2(Whh1[(size_t)(j + 512) * H_ + k]);
                unsigned long long whn = dup2(Whh1[(size_t)(j + 1024) * H_ + k]);
#pragma unroll
                for (int p = 0; p < 4; p++) {
                    unsigned long long h2 =
                        f2u(hs[(bl0 + 2 * p) * H_ + k], hs[(bl0 + 2 * p + 1) * H_ + k]);
                    aIR[p] = fma2(wir, h2, aIR[p]);
                    aIZ[p] = fma2(wiz, h2, aIZ[p]);
                    aIN[p] = fma2(win, h2, aIN[p]);
                    aHR[p] = fma2(whr, h2, aHR[p]);
                    aHZ[p] = fma2(whz, h2, aHZ[p]);
                    aHN[p] = fma2(whn, h2, aHN[p]);
                }
            }
#pragma unroll
            for (int p = 0; p < 4; p++)
#pragma unroll
                for (int off = 16; off > 0; off >>= 1) {
                    aIR[p] = add2(aIR[p], __shfl_xor_sync(0xffffffffu, aIR[p], off));
                    aIZ[p] = add2(aIZ[p], __shfl_xor_sync(0xffffffffu, aIZ[p], off));
                    aIN[p] = add2(aIN[p], __shfl_xor_sync(0xffffffffu, aIN[p], off));
                    aHR[p] = add2(aHR[p], __shfl_xor_sync(0xffffffffu, aHR[p], off));
                    aHZ[p] = add2(aHZ[p], __shfl_xor_sync(0xffffffffu, aHZ[p], off));
                    aHN[p] = add2(aHN[p], __shfl_xor_sync(0xffffffffu, aHN[p], off));
                }
            if (lane < 8) {
                int p = lane >> 1, hi = lane & 1;
                float2 f;
                f = u2f(aIR[p]); float ir  = (hi ? f.y : f.x);
                f = u2f(aIZ[p]); float iz  = (hi ? f.y : f.x);
                f = u2f(aIN[p]); float inn = (hi ? f.y : f.x);
                f = u2f(aHR[p]); float hr  = (hi ? f.y : f.x);
                f = u2f(aHZ[p]); float hz  = (hi ? f.y : f.x);
                f = u2f(aHN[p]); float hn  = (hi ? f.y : f.x);
                float r = sigm(ir + hr + brs);
                float z = sigm(iz + hz + bzs);
                float n = tanhf(inn + bin + r * (hn + bhn));
                int b = bh * 16 + bl0 + lane;
                float h1v = hs[(bl0 + lane) * H_ + j];
                float h2v = (1.f - z) * n + z * h1v;
                g_h[(size_t)b * H_ + j] = h2v;
                g_outs[((size_t)t * B_ + b) * H_ + j] = h2v;
            }
        }
        gbarF(++bt);
    }
}

// ============================================================================
// Projection (R7/R11-proven): mma.sync bf16 hi/lo split, CTA 128x128, BK=32,
// 3-stage cp.async pipeline, 96KB smem -> 2 CTAs/SM.
// ============================================================================
#define PST 32768   // stage stride: Ahi 8K | Alo 8K | Bhi 8K | Blo 8K

__global__ void __launch_bounds__(256, 2)
proj_mma(const float* __restrict__ bout, float* __restrict__ out)
{
    extern __shared__ char psm[];
    const int tid  = threadIdx.x;
    const int lane = tid & 31;
    const int warp = tid >> 5;
    const int wm   = warp & 1;            // 2 warps along M (64 rows each)
    const int wn   = warp >> 1;           // 4 warps along N (32 cols each)
    const int m0   = blockIdx.x * 128;    // m fastest -> B tiles shared via L2
    const int n0   = blockIdx.y * 128;
    const uint32_t sb = smem_u32(psm);

    const int lr = tid >> 1;
    const int cbs = (tid & 1) * 2;        // 16B-chunk base within 64B row

    const int lrA = lane & 15;
    const int lch = lane >> 4;
    const int lx  = (lrA >> 1) & 3;

    float acc[4][4][4];
#pragma unroll
    for (int a = 0; a < 4; a++)
#pragma unroll
        for (int b = 0; b < 4; b++)
#pragma unroll
            for (int c = 0; c < 4; c++) acc[a][b][c] = 0.f;

    const __nv_bfloat16* srcAh = g_Ahi + (size_t)(m0 + lr) * H_;
    const __nv_bfloat16* srcAl = g_Alo + (size_t)(m0 + lr) * H_;
    const __nv_bfloat16* srcBh = g_Whi + (size_t)(n0 + lr) * H_;
    const __nv_bfloat16* srcBl = g_Wlo + (size_t)(n0 + lr) * H_;
    const uint32_t drow = sb + lr * 64;
    const int lsw = (lr >> 1) & 3;

#define ISSUE(kc, s) do {                                                      \
        int k0 = (kc) * 32;                                                    \
        uint32_t stb = drow + (uint32_t)(s) * PST;                             \
        _Pragma("unroll")                                                      \
        for (int c = 0; c < 2; c++) {                                          \
            uint32_t dsw = stb + (uint32_t)(((cbs + c) ^ lsw) << 4);           \
            int ko = k0 + (cbs + c) * 8;                                       \
            cpa16(dsw,         srcAh + ko);                                    \
            cpa16(dsw + 8192,  srcAl + ko);                                    \
            cpa16(dsw + 16384, srcBh + ko);                                    \
            cpa16(dsw + 24576, srcBl + ko);                                    \
        }                                                                      \
        cpa_commit();                                                          \
    } while (0)

    ISSUE(0, 0);
    ISSUE(1, 1);

    for (int kc = 0; kc < 16; kc++) {
        if (kc < 14)       { ISSUE(kc + 2, (kc + 2) % 3); cpa_wait<2>(); }
        else if (kc == 14) { cpa_wait<1>(); }
        else               { cpa_wait<0>(); }
        __syncthreads();

        const int s = kc % 3;
        const uint32_t aRowH = sb + s * PST + (wm * 64 + lrA) * 64;
        const uint32_t aRowL = aRowH + 8192;
        const uint32_t bRowH = sb + s * PST + 16384 + (wn * 32 + lrA) * 64;
        const uint32_t bRowL = bRowH + 8192;

#pragma unroll
        for (int k16 = 0; k16 < 2; k16++) {
            const uint32_t csw = (uint32_t)(((k16 * 2 + lch) ^ lx) << 4);
            uint32_t ah[4][4], al[4][4], bh[2][4], bl[2][4];
#pragma unroll
            for (int fm = 0; fm < 4; fm++) {
                ldsm4(ah[fm], aRowH + fm * 1024 + csw);
                ldsm4(al[fm], aRowL + fm * 1024 + csw);
            }
#pragma unroll
            for (int pr = 0; pr < 2; pr++) {
                ldsm4(bh[pr], bRowH + pr * 1024 + csw);
                ldsm4(bl[pr], bRowL + pr * 1024 + csw);
            }
#pragma unroll
            for (int fm = 0; fm < 4; fm++)
#pragma unroll
                for (int pr = 0; pr < 2; pr++)
#pragma unroll
                    for (int su = 0; su < 2; su++) {
                        float* c = acc[fm][pr * 2 + su];
                        mma16816(c, ah[fm], bh[pr][su], bh[pr][su + 2]);
                        mma16816(c, ah[fm], bl[pr][su], bl[pr][su + 2]);
                        mma16816(c, al[fm], bh[pr][su], bh[pr][su + 2]);
                    }
        }
        __syncthreads();
    }

    // ---- epilogue: direct STG ----
    const int qr = lane >> 2;
    const int qc = (lane & 3) * 2;
#pragma unroll
    for (int fm = 0; fm < 4; fm++) {
        int mA = m0 + wm * 64 + fm * 16 + qr;
        int mB = mA + 8;
        size_t rowA = (size_t)((mA & 31) * T_ + (mA >> 5)) * V_;
        size_t rowB = (size_t)((mB & 31) * T_ + (mB >> 5)) * V_;
#pragma unroll
        for (int fn = 0; fn < 4; fn++) {
            int n = n0 + wn * 32 + fn * 8 + qc;
            float2 bb = *(const float2*)(bout + n);
            float* c = acc[fm][fn];
            *(float2*)(out + rowA + n) = make_float2(c[0] + bb.x, c[1] + bb.y);
            *(float2*)(out + rowB + n) = make_float2(c[2] + bb.x, c[3] + bb.y);
        }
    }
}

// ============================================================================
extern "C" void kernel_launch(void* const* d_in, const int* in_sizes, int n_in,
                              void* d_out, int out_size) {
    (void)in_sizes; (void)n_in; (void)out_size;
    const int*   x    = (const int*)  d_in[0];
    const float* emb  = (const float*)d_in[1];
    const float* Wih  = (const float*)d_in[2];
    const float* Whh  = (const float*)d_in[3];
    const float* bih  = (const float*)d_in[4];
    const float* bhh  = (const float*)d_in[5];
    const float* Wout = (const float*)d_in[6];
    const float* bout = (const float*)d_in[7];
    float* out = (float*)d_out;

    cudaFuncSetAttribute(proj_mma, cudaFuncAttributeMaxDynamicSharedMemorySize, 3 * PST);

    // 1) Wout -> bf16 hi/lo planes
    conv_w<<<(V_ * H_ / 4 + 255) / 256, 256>>>(Wout);

    // 2) gi0 = gather(emb, x) @ Wih0^T + bih0
    gemm_gi0<<<dim3(G3 / 128, (T_ * B_) / 128), 256>>>(emb, Wih, bih, x);

    // 3) zero hidden state (keeps scan in the ncu -s 5 profile slot)
    init_h<<<(B_ * H_ + 255) / 256, 256>>>();

    // 4) 256-step GRU scan (flag/checker/broadcast barrier)
    scan_kernel<<<128, 512>>>(Whh,
                              Wih + (size_t)G3 * H_,
                              Whh + (size_t)G3 * H_,
                              bih + G3,
                              bhh,
                              bhh + G3);

    // 5) outs -> bf16 hi/lo planes
    conv_a<<<(T_ * B_ * H_ / 4 + 255) / 256, 256>>>();

    // 6) logits = outs @ Wout^T + bout  (BK=32, 3-stage, 2 CTAs/SM)
    proj_mma<<<dim3((T_ * B_) / 128, V_ / 128), 256, 3 * PST>>>(bout, out);
}

// round 14
// speedup vs baseline: 1.0499x; 1.0291x over previous
#include <cuda_runtime.h>
#include <cuda_bf16.h>
#include <cstdint>

#define B_  32
#define T_  256
#define V_  32000
#define H_  512
#define G3  1536

// ---------------- scratch (device globals; no allocations allowed) ----------
__device__ float g_gi0[(size_t)T_ * B_ * G3];     // [t][b][3H] layer-0 input gates
__device__ float g_h   [B_ * H_];                 // threaded hidden
__device__ float g_h1  [B_ * H_];                 // hidden after layer 0
__device__ float g_outs[(size_t)T_ * B_ * H_];    // [t][b][H] scan outputs
__device__ __nv_bfloat16 g_Whi[(size_t)V_ * H_];  // Wout bf16 hi plane
__device__ __nv_bfloat16 g_Wlo[(size_t)V_ * H_];  // Wout bf16 lo plane
__device__ __nv_bfloat16 g_Ahi[(size_t)T_ * B_ * H_];
__device__ __nv_bfloat16 g_Alo[(size_t)T_ * B_ * H_];
__device__ __align__(16) volatile unsigned g_flagsV[128];  // barrier arrival flags
__device__ volatile unsigned g_go;                          // barrier release word

// ---------------- packed f32x2 helpers -------------------------------------
__device__ __forceinline__ unsigned long long dup2(float x) {
    unsigned long long r; asm("mov.b64 %0, {%1,%1};" : "=l"(r) : "f"(x)); return r;
}
__device__ __forceinline__ unsigned long long f2u(float x, float y) {
    unsigned long long r; asm("mov.b64 %0, {%1,%2};" : "=l"(r) : "f"(x), "f"(y)); return r;
}
__device__ __forceinline__ float2 u2f(unsigned long long v) {
    float2 f; asm("mov.b64 {%0,%1}, %2;" : "=f"(f.x), "=f"(f.y) : "l"(v)); return f;
}
__device__ __forceinline__ unsigned long long fma2(unsigned long long a,
                                                   unsigned long long b,
                                                   unsigned long long c) {
    unsigned long long d;
    asm("fma.rn.f32x2 %0, %1, %2, %3;" : "=l"(d) : "l"(a), "l"(b), "l"(c));
    return d;
}
__device__ __forceinline__ unsigned long long add2(unsigned long long a,
                                                   unsigned long long b) {
    unsigned long long d;
    asm("add.rn.f32x2 %0, %1, %2;" : "=l"(d) : "l"(a), "l"(b));
    return d;
}
__device__ __forceinline__ float sigm(float x) { return 1.f / (1.f + __expf(-x)); }

__device__ __forceinline__ uint32_t smem_u32(const void* p) {
    uint32_t a;
    asm("{ .reg .u64 t; cvta.to.shared.u64 t, %1; cvt.u32.u64 %0, t; }" : "=r"(a) : "l"(p));
    return a;
}

// ---------------- mma.sync / ldmatrix / cp.async helpers --------------------
__device__ __forceinline__ void ldsm4(uint32_t* r, uint32_t addr) {
    asm volatile("ldmatrix.sync.aligned.m8n8.x4.shared.b16 {%0,%1,%2,%3}, [%4];"
        : "=r"(r[0]), "=r"(r[1]), "=r"(r[2]), "=r"(r[3]) : "r"(addr));
}
__device__ __forceinline__ void mma16816(float* c, const uint32_t* a,
                                         uint32_t b0, uint32_t b1) {
    asm volatile("mma.sync.aligned.m16n8k16.row.col.f32.bf16.bf16.f32 "
        "{%0,%1,%2,%3}, {%4,%5,%6,%7}, {%8,%9}, {%0,%1,%2,%3};"
        : "+f"(c[0]), "+f"(c[1]), "+f"(c[2]), "+f"(c[3])
        : "r"(a[0]), "r"(a[1]), "r"(a[2]), "r"(a[3]), "r"(b0), "r"(b1));
}
__device__ __forceinline__ void cpa16(uint32_t d, const void* s) {
    asm volatile("cp.async.cg.shared.global [%0], [%1], 16;" :: "r"(d), "l"(s) : "memory");
}
__device__ __forceinline__ void cpa_commit() {
    asm volatile("cp.async.commit_group;" ::: "memory");
}
template <int N>
__device__ __forceinline__ void cpa_wait() {
    asm volatile("cp.async.wait_group %0;" :: "n"(N) : "memory");
}

// ---------------- grid barrier: store / checker / broadcast -----------------
__device__ __forceinline__ void gbarF(unsigned target) {
    __syncthreads();
    if (threadIdx.x == 0) {
        __threadfence();
        g_flagsV[blockIdx.x] = target;
    }
    if (blockIdx.x == 0 && threadIdx.x < 32) {
        const unsigned* fp = (const unsigned*)g_flagsV;
        for (;;) {
            uint4 v;
            asm volatile("ld.volatile.global.v4.u32 {%0,%1,%2,%3}, [%4];"
                : "=r"(v.x), "=r"(v.y), "=r"(v.z), "=r"(v.w)
                : "l"(fp + threadIdx.x * 4) : "memory");
            bool ok = (int)(v.x - target) >= 0 && (int)(v.y - target) >= 0 &&
                      (int)(v.z - target) >= 0 && (int)(v.w - target) >= 0;
            if (__all_sync(0xffffffffu, ok)) break;
        }
        if (threadIdx.x == 0) g_go = target;
    }
    if (threadIdx.x == 0) {
        while ((int)(g_go - target) < 0) { }
        __threadfence();
    }
    __syncthreads();
}

// ============================================================================
// bf16 hi/lo split converters
// ============================================================================
__global__ void conv_w(const float* __restrict__ src) {
    int i = blockIdx.x * 256 + threadIdx.x;           // per float4
    if (i >= V_ * H_ / 4) return;
    float4 v = ((const float4*)src)[i];
    __nv_bfloat16 h0 = __float2bfloat16(v.x), h1 = __float2bfloat16(v.y);
    __nv_bfloat16 h2 = __float2bfloat16(v.z), h3 = __float2bfloat16(v.w);
    __nv_bfloat162* hp = (__nv_bfloat162*)g_Whi;
    __nv_bfloat162* lp = (__nv_bfloat162*)g_Wlo;
    hp[i * 2]     = __nv_bfloat162(h0, h1);
    hp[i * 2 + 1] = __nv_bfloat162(h2, h3);
    lp[i * 2]     = __nv_bfloat162(__float2bfloat16(v.x - __bfloat162float(h0)),
                                   __float2bfloat16(v.y - __bfloat162float(h1)));
    lp[i * 2 + 1] = __nv_bfloat162(__float2bfloat16(v.z - __bfloat162float(h2)),
                                   __float2bfloat16(v.w - __bfloat162float(h3)));
}
__global__ void conv_a() {
    int i = blockIdx.x * 256 + threadIdx.x;
    if (i >= T_ * B_ * H_ / 4) return;
    float4 v = ((const float4*)g_outs)[i];
    __nv_bfloat16 h0 = __float2bfloat16(v.x), h1 = __float2bfloat16(v.y);
    __nv_bfloat16 h2 = __float2bfloat16(v.z), h3 = __float2bfloat16(v.w);
    __nv_bfloat162* hp = (__nv_bfloat162*)g_Ahi;
    __nv_bfloat162* lp = (__nv_bfloat162*)g_Alo;
    hp[i * 2]     = __nv_bfloat162(h0, h1);
    hp[i * 2 + 1] = __nv_bfloat162(h2, h3);
    lp[i * 2]     = __nv_bfloat162(__float2bfloat16(v.x - __bfloat162float(h0)),
                                   __float2bfloat16(v.y - __bfloat162float(h1)));
    lp[i * 2 + 1] = __nv_bfloat162(__float2bfloat16(v.z - __bfloat162float(h2)),
                                   __float2bfloat16(v.w - __bfloat162float(h3)));
}

// ============================================================================
// init_h: zero hidden state (keeps scan in the ncu -s 5 profile slot)
// ============================================================================
__global__ void init_h() {
    int i = blockIdx.x * 256 + threadIdx.x;
    if (i < B_ * H_) g_h[i] = 0.f;
}

// ============================================================================
// gi0 = gather(emb, x) @ Wih0^T + bih0   (SIMT GEMM, small: 12.9 GF)
// ============================================================================
__global__ void __launch_bounds__(256, 2)
gemm_gi0(const float* __restrict__ Aemb, const float* __restrict__ Bw,
         const float* __restrict__ bias, const int* __restrict__ xtok)
{
    __shared__ float As[16][132];
    __shared__ float Bs[16][132];
    __shared__ int   rowtok[128];

    const int tid = threadIdx.x;
    const int tx  = tid & 15;
    const int ty  = tid >> 4;
    const int m0  = blockIdx.y * 128;
    const int n0  = blockIdx.x * 128;

    if (tid < 128) {
        int m = m0 + tid;
        rowtok[tid] = xtok[(m & 31) * T_ + (m >> 5)];
    }
    __syncthreads();

    unsigned long long acc[8][4];
#pragma unroll
    for (int i = 0; i < 8; i++)
#pragma unroll
        for (int q = 0; q < 4; q++) acc[i][q] = 0ull;

    for (int k0 = 0; k0 < H_; k0 += 16) {
#pragma unroll
        for (int rep = 0; rep < 2; rep++) {
            int lin = tid + rep * 256;
            int row = lin >> 2;
            int kg  = lin & 3;
            float4 va = *(const float4*)(Aemb + (size_t)rowtok[row] * H_ + k0 + kg * 4);
            As[kg * 4 + 0][row] = va.x; As[kg * 4 + 1][row] = va.y;
            As[kg * 4 + 2][row] = va.z; As[kg * 4 + 3][row] = va.w;
            float4 vb = *(const float4*)(Bw + (size_t)(n0 + row) * H_ + k0 + kg * 4);
            Bs[kg * 4 + 0][row] = vb.x; Bs[kg * 4 + 1][row] = vb.y;
            Bs[kg * 4 + 2][row] = vb.z; Bs[kg * 4 + 3][row] = vb.w;
        }
        __syncthreads();

#pragma unroll
        for (int kk = 0; kk < 16; kk++) {
            float4 a0 = *(const float4*)&As[kk][ty * 8];
            float4 a1 = *(const float4*)&As[kk][ty * 8 + 4];
            const unsigned long long* bp = (const unsigned long long*)&Bs[kk][tx * 8];
            unsigned long long b0 = bp[0], b1 = bp[1], b2 = bp[2], b3 = bp[3];
            unsigned long long ad[8];
            ad[0] = dup2(a0.x); ad[1] = dup2(a0.y); ad[2] = dup2(a0.z); ad[3] = dup2(a0.w);
            ad[4] = dup2(a1.x); ad[5] = dup2(a1.y); ad[6] = dup2(a1.z); ad[7] = dup2(a1.w);
#pragma unroll
            for (int i = 0; i < 8; i++) {
                acc[i][0] = fma2(ad[i], b0, acc[i][0]);
                acc[i][1] = fma2(ad[i], b1, acc[i][1]);
                acc[i][2] = fma2(ad[i], b2, acc[i][2]);
                acc[i][3] = fma2(ad[i], b3, acc[i][3]);
            }
        }
        __syncthreads();
    }

    float bb[8];
#pragma unroll
    for (int q = 0; q < 8; q++) bb[q] = bias[n0 + tx * 8 + q];
#pragma unroll
    for (int i = 0; i < 8; i++) {
        int m = m0 + ty * 8 + i;
        float2 c0 = u2f(acc[i][0]);
        float2 c1 = u2f(acc[i][1]);
        float2 c2 = u2f(acc[i][2]);
        float2 c3 = u2f(acc[i][3]);
        float* crow = g_gi0 + (size_t)m * G3 + n0 + tx * 8;
        *(float4*)(crow)     = make_float4(c0.x + bb[0], c0.y + bb[1], c1.x + bb[2], c1.y + bb[3]);
        *(float4*)(crow + 4) = make_float4(c2.x + bb[4], c2.y + bb[5], c3.x + bb[6], c3.y + bb[7]);
    }
}

// ============================================================================
// Recurrent scan v6: identical structure to R13; ONE change: all recurrent
// weights staged into SMEM once (176KB/block dynamic) -> dot loops read
// conflict-free LDS instead of L2-latency LDG. 128 blocks x 512 threads.
// smem: hs 32KB | w0s 48KB (8j x 3g x 512) | w1s 96KB (8j x 6g x 512)
// ============================================================================
#define SCAN_SMEM (32768 + 49152 + 98304)

__global__ void __launch_bounds__(512, 1)
scan_kernel(const float* __restrict__ Whh0,
            const float* __restrict__ Wih1,
            const float* __restrict__ Whh1,
            const float* __restrict__ bih1,
            const float* __restrict__ bhh0,
            const float* __restrict__ bhh1)
{
    extern __shared__ __align__(16) float ssm[];
    float* hs  = ssm;                  // [16b][512]
    float* w0s = ssm + 8192;           // [(jj*3+g)*512 + k]
    float* w1s = ssm + 8192 + 12288;   // [(jj*6+g)*512 + k]

    const int tid  = threadIdx.x;
    const int bid  = blockIdx.x;
    const int lane = tid & 31;
    const int wid  = tid >> 5;
    const int jj   = wid >> 1;            // 0..7
    const int bgl  = wid & 1;             // 0..1 (8-batch group within slab)
    const int jb   = bid >> 1;            // 0..63 (j-slice)
    const int bh   = bid & 1;             // batch half (16 batches)
    const int j    = jb * 8 + jj;         // 0..511
    const int bl0  = bgl * 8;             // local batch base in slab
    const int jb8  = jb * 8;

    // ---- stage ALL recurrent weights for this block's 8 j's into smem ----
    for (int i = tid; i < 3072; i += 512) {            // w0: 8jj x 3g x 128 f4
        int jj2 = i / 384, r = i % 384, g = r >> 7, k4 = (r & 127) * 4;
        int jrow = jb8 + jj2;
        *(float4*)&w0s[(jj2 * 3 + g) * 512 + k4] =
            *(const float4*)&Whh0[((size_t)(g * 512 + jrow)) * H_ + k4];
    }
    for (int i = tid; i < 6144; i += 512) {            // w1: 8jj x 6g x 128 f4
        int jj2 = i / 768, r = i % 768, g = r >> 7, k4 = (r & 127) * 4;
        int jrow = jb8 + jj2;
        const float* src = (g < 3) ? Wih1 : Whh1;
        int gg = (g < 3) ? g : g - 3;
        *(float4*)&w1s[(jj2 * 6 + g) * 512 + k4] =
            *(const float4*)&src[((size_t)(gg * 512 + jrow)) * H_ + k4];
    }

    // ---- loop-invariant biases ----
    const float b0r = bhh0[j], b0z = bhh0[j + 512], b0n = bhh0[j + 1024];
    const float brs = bih1[j] + bhh1[j];
    const float bzs = bih1[j + 512] + bhh1[j + 512];
    const float bin = bih1[j + 1024];
    const float bhn = bhh1[j + 1024];

    const float* w0p = w0s + (jj * 3) * 512;
    const float* w1p = w1s + (jj * 6) * 512;

    unsigned bt = g_go;   // replay-safe relative barrier base

    for (int t = 0; t < T_; t++) {
        // gi0 prefetch (hidden under staging + L0 dot)
        float giR = 0.f, giZ = 0.f, giN = 0.f;
        if (lane < 8) {
            const float* gp = g_gi0 + ((size_t)t * B_ + bh * 16 + bl0 + lane) * G3;
            giR = gp[j]; giZ = gp[j + 512]; giN = gp[j + 1024];
        }

        // ---- stage h slab (16 batches, 32 KB) ----
        for (int i = tid; i < 2048; i += 512)
            *(float4*)&hs[i * 4] = *(const float4*)&g_h[bh * 16 * H_ + i * 4];
        __syncthreads();

        // ---- layer 0 dot (weights from smem) ----
        {
            unsigned long long aR[4], aZ[4], aN[4];
#pragma unroll
            for (int p = 0; p < 4; p++) { aR[p] = 0; aZ[p] = 0; aN[p] = 0; }
#pragma unroll 4
            for (int k = lane; k < H_; k += 32) {
                unsigned long long wr2 = dup2(w0p[k]);
                unsigned long long wz2 = dup2(w0p[512 + k]);
                unsigned long long wn2 = dup2(w0p[1024 + k]);
#pragma unroll
                for (int p = 0; p < 4; p++) {
                    unsigned long long h2 =
                        f2u(hs[(bl0 + 2 * p) * H_ + k], hs[(bl0 + 2 * p + 1) * H_ + k]);
                    aR[p] = fma2(wr2, h2, aR[p]);
                    aZ[p] = fma2(wz2, h2, aZ[p]);
                    aN[p] = fma2(wn2, h2, aN[p]);
                }
            }
#pragma unroll
            for (int p = 0; p < 4; p++)
#pragma unroll
                for (int off = 16; off > 0; off >>= 1) {
                    aR[p] = add2(aR[p], __shfl_xor_sync(0xffffffffu, aR[p], off));
                    aZ[p] = add2(aZ[p], __shfl_xor_sync(0xffffffffu, aZ[p], off));
                    aN[p] = add2(aN[p], __shfl_xor_sync(0xffffffffu, aN[p], off));
                }
            if (lane < 8) {
                int p = lane >> 1, hi = lane & 1;
                float2 fr = u2f(aR[p]), fz = u2f(aZ[p]), fn = u2f(aN[p]);
                float ghr = (hi ? fr.y : fr.x) + b0r;
                float ghz = (hi ? fz.y : fz.x) + b0z;
                float ghn = (hi ? fn.y : fn.x) + b0n;
                float r = sigm(giR + ghr);
                float z = sigm(giZ + ghz);
                float n = tanhf(giN + r * ghn);
                int b = bh * 16 + bl0 + lane;
                float hold = hs[(bl0 + lane) * H_ + j];
                g_h1[(size_t)b * H_ + j] = (1.f - z) * n + z * hold;
            }
        }
        gbarF(++bt);

        // ---- stage h1 slab ----
        for (int i = tid; i < 2048; i += 512)
            *(float4*)&hs[i * 4] = *(const float4*)&g_h1[bh * 16 * H_ + i * 4];
        __syncthreads();

        // ---- layer 1 dot (weights from smem) ----
        {
            unsigned long long aIR[4], aIZ[4], aIN[4], aHR[4], aHZ[4], aHN[4];
#pragma unroll
            for (int p = 0; p < 4; p++) {
                aIR[p] = 0; aIZ[p] = 0; aIN[p] = 0;
                aHR[p] = 0; aHZ[p] = 0; aHN[p] = 0;
            }
#pragma unroll 4
            for (int k = lane; k < H_; k += 32) {
                unsigned long long wir = dup2(w1p[k]);
                unsigned long long wiz = dup2(w1p[512 + k]);
                unsigned long long win = dup2(w1p[1024 + k]);
                unsigned long long whr = dup2(w1p[1536 + k]);
                unsigned long long whz = dup2(w1p[2048 + k]);
                unsigned long long whn = dup2(w1p[2560 + k]);
#pragma unroll
                for (int p = 0; p < 4; p++) {
                    unsigned long long h2 =
                        f2u(hs[(bl0 + 2 * p) * H_ + k], hs[(bl0 + 2 * p + 1) * H_ + k]);
                    aIR[p] = fma2(wir, h2, aIR[p]);
                    aIZ[p] = fma2(wiz, h2, aIZ[p]);
                    aIN[p] = fma2(win, h2, aIN[p]);
                    aHR[p] = fma2(whr, h2, aHR[p]);
                    aHZ[p] = fma2(whz, h2, aHZ[p]);
                    aHN[p] = fma2(whn, h2, aHN[p]);
                }
            }
#pragma unroll
            for (int p = 0; p < 4; p++)
#pragma unroll
                for (int off = 16; off > 0; off >>= 1) {
                    aIR[p] = add2(aIR[p], __shfl_xor_sync(0xffffffffu, aIR[p], off));
                    aIZ[p] = add2(aIZ[p], __shfl_xor_sync(0xffffffffu, aIZ[p], off));
                    aIN[p] = add2(aIN[p], __shfl_xor_sync(0xffffffffu, aIN[p], off));
                    aHR[p] = add2(aHR[p], __shfl_xor_sync(0xffffffffu, aHR[p], off));
                    aHZ[p] = add2(aHZ[p], __shfl_xor_sync(0xffffffffu, aHZ[p], off));
                    aHN[p] = add2(aHN[p], __shfl_xor_sync(0xffffffffu, aHN[p], off));
                }
            if (lane < 8) {
                int p = lane >> 1, hi = lane & 1;
                float2 f;
                f = u2f(aIR[p]); float ir  = (hi ? f.y : f.x);
                f = u2f(aIZ[p]); float iz  = (hi ? f.y : f.x);
                f = u2f(aIN[p]); float inn = (hi ? f.y : f.x);
                f = u2f(aHR[p]); float hr  = (hi ? f.y : f.x);
                f = u2f(aHZ[p]); float hz  = (hi ? f.y : f.x);
                f = u2f(aHN[p]); float hn  = (hi ? f.y : f.x);
                float r = sigm(ir + hr + brs);
                float z = sigm(iz + hz + bzs);
                float n = tanhf(inn + bin + r * (hn + bhn));
                int b = bh * 16 + bl0 + lane;
                float h1v = hs[(bl0 + lane) * H_ + j];
                float h2v = (1.f - z) * n + z * h1v;
                g_h[(size_t)b * H_ + j] = h2v;
                g_outs[((size_t)t * B_ + b) * H_ + j] = h2v;
            }
        }
        gbarF(++bt);
    }
}

// ============================================================================
// Projection (R7/R11-proven): mma.sync bf16 hi/lo split, CTA 128x128, BK=32,
// 3-stage cp.async pipeline, 96KB smem -> 2 CTAs/SM.
// ============================================================================
#define PST 32768   // stage stride: Ahi 8K | Alo 8K | Bhi 8K | Blo 8K

__global__ void __launch_bounds__(256, 2)
proj_mma(const float* __restrict__ bout, float* __restrict__ out)
{
    extern __shared__ char psm[];
    const int tid  = threadIdx.x;
    const int lane = tid & 31;
    const int warp = tid >> 5;
    const int wm   = warp & 1;            // 2 warps along M (64 rows each)
    const int wn   = warp >> 1;           // 4 warps along N (32 cols each)
    const int m0   = blockIdx.x * 128;    // m fastest -> B tiles shared via L2
    const int n0   = blockIdx.y * 128;
    const uint32_t sb = smem_u32(psm);

    const int lr = tid >> 1;
    const int cbs = (tid & 1) * 2;        // 16B-chunk base within 64B row

    const int lrA = lane & 15;
    const int lch = lane >> 4;
    const int lx  = (lrA >> 1) & 3;

    float acc[4][4][4];
#pragma unroll
    for (int a = 0; a < 4; a++)
#pragma unroll
        for (int b = 0; b < 4; b++)
#pragma unroll
            for (int c = 0; c < 4; c++) acc[a][b][c] = 0.f;

    const __nv_bfloat16* srcAh = g_Ahi + (size_t)(m0 + lr) * H_;
    const __nv_bfloat16* srcAl = g_Alo + (size_t)(m0 + lr) * H_;
    const __nv_bfloat16* srcBh = g_Whi + (size_t)(n0 + lr) * H_;
    const __nv_bfloat16* srcBl = g_Wlo + (size_t)(n0 + lr) * H_;
    const uint32_t drow = sb + lr * 64;
    const int lsw = (lr >> 1) & 3;

#define ISSUE(kc, s) do {                                                      \
        int k0 = (kc) * 32;                                                    \
        uint32_t stb = drow + (uint32_t)(s) * PST;                             \
        _Pragma("unroll")                                                      \
        for (int c = 0; c < 2; c++) {                                          \
            uint32_t dsw = stb + (uint32_t)(((cbs + c) ^ lsw) << 4);           \
            int ko = k0 + (cbs + c) * 8;                                       \
            cpa16(dsw,         srcAh + ko);                                    \
            cpa16(dsw + 8192,  srcAl + ko);                                    \
            cpa16(dsw + 16384, srcBh + ko);                                    \
            cpa16(dsw + 24576, srcBl + ko);                                    \
        }                                                                      \
        cpa_commit();                                                          \
    } while (0)

    ISSUE(0, 0);
    ISSUE(1, 1);

    for (int kc = 0; kc < 16; kc++) {
        if (kc < 14)       { ISSUE(kc + 2, (kc + 2) % 3); cpa_wait<2>(); }
        else if (kc == 14) { cpa_wait<1>(); }
        else               { cpa_wait<0>(); }
        __syncthreads();

        const int s = kc % 3;
        const uint32_t aRowH = sb + s * PST + (wm * 64 + lrA) * 64;
        const uint32_t aRowL = aRowH + 8192;
        const uint32_t bRowH = sb + s * PST + 16384 + (wn * 32 + lrA) * 64;
        const uint32_t bRowL = bRowH + 8192;

#pragma unroll
        for (int k16 = 0; k16 < 2; k16++) {
            const uint32_t csw = (uint32_t)(((k16 * 2 + lch) ^ lx) << 4);
            uint32_t ah[4][4], al[4][4], bh[2][4], bl[2][4];
#pragma unroll
            for (int fm = 0; fm < 4; fm++) {
                ldsm4(ah[fm], aRowH + fm * 1024 + csw);
                ldsm4(al[fm], aRowL + fm * 1024 + csw);
            }
#pragma unroll
            for (int pr = 0; pr < 2; pr++) {
                ldsm4(bh[pr], bRowH + pr * 1024 + csw);
                ldsm4(bl[pr], bRowL + pr * 1024 + csw);
            }
#pragma unroll
            for (int fm = 0; fm < 4; fm++)
#pragma unroll
                for (int pr = 0; pr < 2; pr++)
#pragma unroll
                    for (int su = 0; su < 2; su++) {
                        float* c = acc[fm][pr * 2 + su];
                        mma16816(c, ah[fm], bh[pr][su], bh[pr][su + 2]);
                        mma16816(c, ah[fm], bl[pr][su], bl[pr][su + 2]);
                        mma16816(c, al[fm], bh[pr][su], bh[pr][su + 2]);
                    }
        }
        __syncthreads();
    }

    // ---- epilogue: direct STG ----
    const int qr = lane >> 2;
    const int qc = (lane & 3) * 2;
#pragma unroll
    for (int fm = 0; fm < 4; fm++) {
        int mA = m0 + wm * 64 + fm * 16 + qr;
        int mB = mA + 8;
        size_t rowA = (size_t)((mA & 31) * T_ + (mA >> 5)) * V_;
        size_t rowB = (size_t)((mB & 31) * T_ + (mB >> 5)) * V_;
#pragma unroll
        for (int fn = 0; fn < 4; fn++) {
            int n = n0 + wn * 32 + fn * 8 + qc;
            float2 bb = *(const float2*)(bout + n);
            float* c = acc[fm][fn];
            *(float2*)(out + rowA + n) = make_float2(c[0] + bb.x, c[1] + bb.y);
            *(float2*)(out + rowB + n) = make_float2(c[2] + bb.x, c[3] + bb.y);
        }
    }
}

// ============================================================================
extern "C" void kernel_launch(void* const* d_in, const int* in_sizes, int n_in,
                              void* d_out, int out_size) {
    (void)in_sizes; (void)n_in; (void)out_size;
    const int*   x    = (const int*)  d_in[0];
    const float* emb  = (const float*)d_in[1];
    const float* Wih  = (const float*)d_in[2];
    const float* Whh  = (const float*)d_in[3];
    const float* bih  = (const float*)d_in[4];
    const float* bhh  = (const float*)d_in[5];
    const float* Wout = (const float*)d_in[6];
    const float* bout = (const float*)d_in[7];
    float* out = (float*)d_out;

    cudaFuncSetAttribute(proj_mma, cudaFuncAttributeMaxDynamicSharedMemorySize, 3 * PST);
    cudaFuncSetAttribute(scan_kernel, cudaFuncAttributeMaxDynamicSharedMemorySize, SCAN_SMEM);

    // 1) Wout -> bf16 hi/lo planes
    conv_w<<<(V_ * H_ / 4 + 255) / 256, 256>>>(Wout);

    // 2) gi0 = gather(emb, x) @ Wih0^T + bih0
    gemm_gi0<<<dim3(G3 / 128, (T_ * B_) / 128), 256>>>(emb, Wih, bih, x);

    // 3) zero hidden state (keeps scan in the ncu -s 5 profile slot)
    init_h<<<(B_ * H_ + 255) / 256, 256>>>();

    // 4) 256-step GRU scan (weights SMEM-resident, flag barrier)
    scan_kernel<<<128, 512, SCAN_SMEM>>>(Whh,
                                         Wih + (size_t)G3 * H_,
                                         Whh + (size_t)G3 * H_,
                                         bih + G3,
                                         bhh,
                                         bhh + G3);

    // 5) outs -> bf16 hi/lo planes
    conv_a<<<(T_ * B_ * H_ / 4 + 255) / 256, 256>>>();

    // 6) logits = outs @ Wout^T + bout  (BK=32, 3-stage, 2 CTAs/SM)
    proj_mma<<<dim3((T_ * B_) / 128, V_ / 128), 256, 3 * PST>>>(bout, out);
}